// round 6
// baseline (speedup 1.0000x reference)
#include <cuda_runtime.h>
#include <cuda_bf16.h>
#include <cstdint>

// Fused BN(affine) -> ReLU -> 2x2 AvgPool(stride 2) -> 1x1 Conv (channel GEMM)
// x:           [N=32, C_in=32, H=256, W=256] f32
// conv_weight: [C_in=32, C_out=16] f32 (row-major, w[c*16+d])
// bn_scale/bn_bias: [32] f32
// out:         [N=32, C_out=16, 128, 128] f32
//
// R6: fix wave quantization. R5: 1024 blocks / (4/SM*148) = 1.73 gens ->
// 86.5% fill; 86.5% * ~86% intrinsic = the measured 74% DRAM. Split C_OUT
// across thread pairs (half = tid>>7): accumulators 16 regs instead of 32 ->
// 7 blocks/SM fits (regs<=36, smem 28.5KB). Grid 2048 / 1036 slots = 1.98
// gens -> 98.8% fill. Staging ring is now block-shared (both halves read the
// same pixels), ordered by one __syncthreads per channel.

#define C_IN  32
#define C_OUT 16
#define HIN   256
#define WIN   256
#define POUT  128
#define PLANE (POUT * POUT)   // 16384
#define CSTRIDE (HIN * WIN)   // 65536
#define PIPE  6

__device__ __forceinline__ unsigned long long pack_f32x2(float lo, float hi) {
    unsigned long long r;
    asm("mov.b64 %0, {%1, %2};" : "=l"(r) : "f"(lo), "f"(hi));
    return r;
}

__device__ __forceinline__ void fma_f32x2(unsigned long long& acc,
                                          unsigned long long a,
                                          unsigned long long b) {
    asm("fma.rn.f32x2 %0, %1, %2, %0;" : "+l"(acc) : "l"(a), "l"(b));
}

__device__ __forceinline__ void cp16(unsigned int smem_dst, const float* gmem_src) {
    asm volatile("cp.async.cg.shared.global.L2::256B [%0], [%1], 16;"
                 :: "r"(smem_dst), "l"(gmem_src));
}

__device__ __forceinline__ void cp_commit() {
    asm volatile("cp.async.commit_group;");
}

template <int N>
__device__ __forceinline__ void cp_wait() {
    asm volatile("cp.async.wait_group %0;" :: "n"(N));
}

__device__ __forceinline__ unsigned int smem_u32(const void* p) {
    unsigned int a;
    asm("{ .reg .u64 t; cvta.to.shared.u64 t, %1; cvt.u32.u64 %0, t; }"
        : "=r"(a) : "l"(p));
    return a;
}

__global__ __launch_bounds__(256, 7) void fused_bn_relu_pool_conv(
    const float* __restrict__ x,
    const float* __restrict__ wmat,
    const float* __restrict__ scale,
    const float* __restrict__ bias,
    float* __restrict__ out)
{
    // Staging ring: stage[k][row][slot], slot = pixel-pair (128 per block)
    __shared__ float4 stage[PIPE][2][128];              // PIPE * 4 KB
    __shared__ float2 s_w2[C_IN * C_OUT];               // {0.25w, 0.25w}, 4 KB
    __shared__ float  s_sc[C_IN];
    __shared__ float  s_bi[C_IN];

    const int tid = threadIdx.x;
    for (int i = tid; i < C_IN * C_OUT; i += 256) {
        const float w = 0.25f * wmat[i];
        s_w2[i] = make_float2(w, w);
    }
    if (tid < C_IN) { s_sc[tid] = scale[tid]; s_bi[tid] = bias[tid]; }

    // slot = pixel-pair index within block; half selects output channels d in
    // [half*8, half*8+8). Producer role: thread loads row `half` of its slot.
    const int slot = tid & 127;
    const int half = tid >> 7;

    const int g   = blockIdx.x * 128 + slot;
    const int n   = g >> 13;          // 8192 pair-slots per image
    const int rem = g & 8191;
    const int h2  = rem >> 6;         // 0..127
    const int wq  = rem & 63;         // 0..63

    // This thread's producer source: row `half` of the 2x2 window
    const float* src = x + ((size_t)n * C_IN * HIN + 2 * h2 + half) * WIN + 4 * wq;
    // Producer dst base for slot 0 of the ring
    const unsigned int dst0 = smem_u32(&stage[0][half][slot]);

    __syncthreads();   // weights/scales visible

    // Prologue: issue channels 0..PIPE-2
#pragma unroll
    for (int k = 0; k < PIPE - 1; k++) {
        cp16(dst0 + (unsigned int)k * 4096u, src + (size_t)k * CSTRIDE);
        cp_commit();
    }

    unsigned long long acc[C_OUT / 2];
#pragma unroll
    for (int j = 0; j < C_OUT / 2; j++) acc[j] = 0ULL;

#pragma unroll
    for (int c = 0; c < C_IN; c++) {
        // Wait until channel c's group has landed.
        if (c + PIPE - 1 < C_IN) {
            cp_wait<PIPE - 2>();
        } else {
            switch (C_IN - 1 - c) {
                case 4: cp_wait<4>(); break;
                case 3: cp_wait<3>(); break;
                case 2: cp_wait<2>(); break;
                case 1: cp_wait<1>(); break;
                default: cp_wait<0>(); break;
            }
        }
        // All threads see channel c's data AND are done consuming channel c-1
        // (whose slot we are about to overwrite).
        __syncthreads();

        // Prefetch channel c+PIPE-1 into the slot freed by channel c-1.
        if (c + PIPE - 1 < C_IN) {
            const int ck = c + PIPE - 1;
            cp16(dst0 + (unsigned int)(ck % PIPE) * 4096u, src + (size_t)ck * CSTRIDE);
            cp_commit();
        }

        const int k = c % PIPE;
        const float4 r0 = stage[k][0][slot];
        const float4 r1 = stage[k][1][slot];
        const float sc = s_sc[c];
        const float bi = s_bi[c];

        // BN + ReLU on all 8 taps (duplicated across the two halves)
        const float v0 = fmaxf(fmaf(r0.x, sc, bi), 0.0f);
        const float v1 = fmaxf(fmaf(r0.y, sc, bi), 0.0f);
        const float v2 = fmaxf(fmaf(r0.z, sc, bi), 0.0f);
        const float v3 = fmaxf(fmaf(r0.w, sc, bi), 0.0f);
        const float u0 = fmaxf(fmaf(r1.x, sc, bi), 0.0f);
        const float u1 = fmaxf(fmaf(r1.y, sc, bi), 0.0f);
        const float u2 = fmaxf(fmaf(r1.z, sc, bi), 0.0f);
        const float u3 = fmaxf(fmaf(r1.w, sc, bi), 0.0f);

        const float p0 = (v0 + v1) + (u0 + u1);
        const float p1 = (v2 + v3) + (u2 + u3);
        const unsigned long long p = pack_f32x2(p0, p1);

        // This half's 8 output channels
        const unsigned long long* w2 = reinterpret_cast<const unsigned long long*>(
            &s_w2[c * C_OUT + half * (C_OUT / 2)]);
#pragma unroll
        for (int j = 0; j < C_OUT / 2; j++) {
            fma_f32x2(acc[j], p, w2[j]);
        }
    }

    // Output: channels d = half*8 + j, pixels {2*wq, 2*wq+1} of row h2
    float2* o = reinterpret_cast<float2*>(
        out + ((size_t)n * C_OUT + half * (C_OUT / 2)) * PLANE + h2 * POUT + 2 * wq);
#pragma unroll
    for (int j = 0; j < C_OUT / 2; j++) {
        o[(size_t)j * (PLANE / 2)] = *reinterpret_cast<const float2*>(&acc[j]);
    }
}

extern "C" void kernel_launch(void* const* d_in, const int* in_sizes, int n_in,
                              void* d_out, int out_size)
{
    const float* x     = (const float*)d_in[0];
    const float* wmat  = (const float*)d_in[1];
    const float* scale = (const float*)d_in[2];
    const float* bias  = (const float*)d_in[3];
    float* out         = (float*)d_out;

    // 262144 pixel-pairs, 128 per block, 2 d-halves -> 2048 blocks x 256
    fused_bn_relu_pool_conv<<<2048, 256>>>(x, wmat, scale, bias, out);
}

// round 8
// speedup vs baseline: 1.0320x; 1.0320x over previous
#include <cuda_runtime.h>
#include <cuda_bf16.h>
#include <cstdint>

// Fused BN(affine) -> ReLU -> 2x2 AvgPool(stride 2) -> 1x1 Conv (channel GEMM)
// x:           [N=32, C_in=32, H=256, W=256] f32
// conv_weight: [C_in=32, C_out=16] f32 (row-major, w[c*16+d])
// bn_scale/bn_bias: [32] f32
// out:         [N=32, C_out=16, 128, 128] f32
//
// R7: R5 body unchanged (2 pooled pixels/thread, per-thread cp.async ring,
// no in-loop barriers) made PERSISTENT: grid = 592 = 4 blocks/SM * 148 SMs,
// exactly one resident wave; each thread grid-strides over its 1-2 pixel
// pairs. Eliminates the wave-2 block-droop tail of R5 (1024 blocks / 592
// slots) without R3/R6's per-byte instruction & smem overhead.

#define C_IN  32
#define C_OUT 16
#define HIN   256
#define WIN   256
#define POUT  128
#define CSTRIDE (HIN * WIN)      // 65536
#define PIPE  5
#define NBLOCKS 592              // 4 * 148
#define TOTAL_PAIRS (32 * 128 * 64)   // 262144
#define GSTRIDE (NBLOCKS * 256)  // 151552

__device__ __forceinline__ unsigned long long pack_f32x2(float lo, float hi) {
    unsigned long long r;
    asm("mov.b64 %0, {%1, %2};" : "=l"(r) : "f"(lo), "f"(hi));
    return r;
}

__device__ __forceinline__ void fma_f32x2(unsigned long long& acc,
                                          unsigned long long a,
                                          unsigned long long b) {
    asm("fma.rn.f32x2 %0, %1, %2, %0;" : "+l"(acc) : "l"(a), "l"(b));
}

__device__ __forceinline__ void cp16(unsigned int smem_dst, const float* gmem_src) {
    asm volatile("cp.async.cg.shared.global.L2::256B [%0], [%1], 16;"
                 :: "r"(smem_dst), "l"(gmem_src));
}

__device__ __forceinline__ void cp_commit() {
    asm volatile("cp.async.commit_group;");
}

template <int N>
__device__ __forceinline__ void cp_wait() {
    asm volatile("cp.async.wait_group %0;" :: "n"(N));
}

__device__ __forceinline__ unsigned int smem_u32(const void* p) {
    unsigned int a;
    asm("{ .reg .u64 t; cvta.to.shared.u64 t, %1; cvt.u32.u64 %0, t; }"
        : "=r"(a) : "l"(p));
    return a;
}

__global__ __launch_bounds__(256, 4) void fused_bn_relu_pool_conv(
    const float* __restrict__ x,
    const float* __restrict__ wmat,
    const float* __restrict__ scale,
    const float* __restrict__ bias,
    float* __restrict__ out)
{
    // Per-thread staging ring: stage[k][r][tid] (r = row 0/1 of the 2x2 window)
    __shared__ float4 stage[PIPE][2][256];
    // Packed weights {0.25*w, 0.25*w} per (c,d): 4 KB
    __shared__ float2 s_w2[C_IN * C_OUT];
    __shared__ float  s_sc[C_IN];
    __shared__ float  s_bi[C_IN];

    const int tid = threadIdx.x;
    for (int i = tid; i < C_IN * C_OUT; i += 256) {
        const float w = 0.25f * wmat[i];
        s_w2[i] = make_float2(w, w);
    }
    if (tid < C_IN) { s_sc[tid] = scale[tid]; s_bi[tid] = bias[tid]; }
    __syncthreads();

    // smem base for this thread's ring slots; slot (k,r) at st0 + (k*2+r)*4096
    const unsigned int st0 = smem_u32(&stage[0][0][tid]);

    const int g0 = blockIdx.x * 256 + tid;

    for (int g = g0; g < TOTAL_PAIRS; g += GSTRIDE) {
        // Mapping: image n, pooled row h2, pooled columns {2*wq, 2*wq+1}
        const int n   = g >> 13;          // 8192 pair-slots per image
        const int rem = g & 8191;
        const int h2  = rem >> 6;         // 0..127
        const int wq  = rem & 63;         // 0..63

        const float* base = x + ((size_t)n * C_IN * HIN + 2 * h2) * WIN + 4 * wq;

        // Prologue: prime PIPE-1 channel groups
#pragma unroll
        for (int k = 0; k < PIPE - 1; k++) {
            cp16(st0 + (unsigned int)(k * 2 + 0) * 4096u, base + (size_t)k * CSTRIDE);
            cp16(st0 + (unsigned int)(k * 2 + 1) * 4096u, base + (size_t)k * CSTRIDE + WIN);
            cp_commit();
        }

        unsigned long long acc[C_OUT];
#pragma unroll
        for (int d = 0; d < C_OUT; d++) acc[d] = 0ULL;

#pragma unroll
        for (int c = 0; c < C_IN; c++) {
            // Issue the load PIPE-1 channels ahead, then wait for channel c.
            if (c + PIPE - 1 < C_IN) {
                const int ck = c + PIPE - 1;
                const int k  = ck % PIPE;
                cp16(st0 + (unsigned int)(k * 2 + 0) * 4096u, base + (size_t)ck * CSTRIDE);
                cp16(st0 + (unsigned int)(k * 2 + 1) * 4096u, base + (size_t)ck * CSTRIDE + WIN);
                cp_commit();
                cp_wait<PIPE - 1>();   // channels <= c complete (FIFO)
            } else {
                switch (C_IN - 1 - c) {
                    case 3: cp_wait<3>(); break;
                    case 2: cp_wait<2>(); break;
                    case 1: cp_wait<1>(); break;
                    default: cp_wait<0>(); break;
                }
            }

            const int k = c % PIPE;
            const float4 r0 = stage[k][0][tid];
            const float4 r1 = stage[k][1][tid];
            const float sc = s_sc[c];
            const float bi = s_bi[c];

            // BN + ReLU on all 8 taps
            const float v0 = fmaxf(fmaf(r0.x, sc, bi), 0.0f);
            const float v1 = fmaxf(fmaf(r0.y, sc, bi), 0.0f);
            const float v2 = fmaxf(fmaf(r0.z, sc, bi), 0.0f);
            const float v3 = fmaxf(fmaf(r0.w, sc, bi), 0.0f);
            const float u0 = fmaxf(fmaf(r1.x, sc, bi), 0.0f);
            const float u1 = fmaxf(fmaf(r1.y, sc, bi), 0.0f);
            const float u2 = fmaxf(fmaf(r1.z, sc, bi), 0.0f);
            const float u3 = fmaxf(fmaf(r1.w, sc, bi), 0.0f);

            // 2x2 pool sums (the *0.25 is folded into the weights)
            const float p0 = (v0 + v1) + (u0 + u1);
            const float p1 = (v2 + v3) + (u2 + u3);
            const unsigned long long p = pack_f32x2(p0, p1);

            const unsigned long long* w2 =
                reinterpret_cast<const unsigned long long*>(&s_w2[c * C_OUT]);
#pragma unroll
            for (int d = 0; d < C_OUT; d++) {
                fma_f32x2(acc[d], p, w2[d]);
            }
        }

        // Output: out[n][d][h2][2*wq .. 2*wq+1]; acc bits are exactly {p0,p1}
        float2* o = reinterpret_cast<float2*>(
            out + (size_t)n * C_OUT * (POUT * POUT) + h2 * POUT + 2 * wq);
#pragma unroll
        for (int d = 0; d < C_OUT; d++) {
            o[(size_t)d * (POUT * POUT / 2)] =
                *reinterpret_cast<const float2*>(&acc[d]);
        }
    }
}

extern "C" void kernel_launch(void* const* d_in, const int* in_sizes, int n_in,
                              void* d_out, int out_size)
{
    const float* x     = (const float*)d_in[0];
    const float* wmat  = (const float*)d_in[1];
    const float* scale = (const float*)d_in[2];
    const float* bias  = (const float*)d_in[3];
    float* out         = (float*)d_out;

    // Persistent single wave: 592 blocks = 4/SM * 148 SMs
    fused_bn_relu_pool_conv<<<NBLOCKS, 256>>>(x, wmat, scale, bias, out);
}

// round 9
// speedup vs baseline: 1.0762x; 1.0429x over previous
#include <cuda_runtime.h>
#include <cuda_bf16.h>
#include <cstdint>

// Fused BN(affine) -> ReLU -> 2x2 AvgPool(stride 2) -> 1x1 Conv (channel GEMM)
// x:           [N=32, C_in=32, H=256, W=256] f32
// conv_weight: [C_in=32, C_out=16] f32 (row-major, w[c*16+d])
// bn_scale/bn_bias: [32] f32
// out:         [N=32, C_out=16, 128, 128] f32
//
// R8: persistent WITHOUT the R7 drain bubble. Ring depth 4 (slot = c&3;
// 32 % 4 == 0 so slots line up across iterations). The tail steps of each
// grid-stride iteration (c=29..31) issue channels 0..2 of the NEXT pixel-pair
// instead of draining; the final iteration issues empty commit_groups to keep
// wait_group counts uniform. Pipe stays 3 groups deep continuously.
// Grid 592 = 4/SM * 148 SMs -> 98.8% fill, single resident wave.

#define C_IN  32
#define C_OUT 16
#define HIN   256
#define WIN   256
#define POUT  128
#define CSTRIDE (HIN * WIN)      // 65536
#define NBLOCKS 592              // 4 * 148
#define TOTAL_PAIRS (32 * 128 * 64)   // 262144
#define GSTRIDE (NBLOCKS * 256)  // 151552

__device__ __forceinline__ unsigned long long pack_f32x2(float lo, float hi) {
    unsigned long long r;
    asm("mov.b64 %0, {%1, %2};" : "=l"(r) : "f"(lo), "f"(hi));
    return r;
}

__device__ __forceinline__ void fma_f32x2(unsigned long long& acc,
                                          unsigned long long a,
                                          unsigned long long b) {
    asm("fma.rn.f32x2 %0, %1, %2, %0;" : "+l"(acc) : "l"(a), "l"(b));
}

__device__ __forceinline__ void cp16(unsigned int smem_dst, const float* gmem_src) {
    asm volatile("cp.async.cg.shared.global.L2::256B [%0], [%1], 16;"
                 :: "r"(smem_dst), "l"(gmem_src));
}

__device__ __forceinline__ void cp_commit() {
    asm volatile("cp.async.commit_group;");
}

template <int N>
__device__ __forceinline__ void cp_wait() {
    asm volatile("cp.async.wait_group %0;" :: "n"(N));
}

__device__ __forceinline__ unsigned int smem_u32(const void* p) {
    unsigned int a;
    asm("{ .reg .u64 t; cvta.to.shared.u64 t, %1; cvt.u32.u64 %0, t; }"
        : "=r"(a) : "l"(p));
    return a;
}

__device__ __forceinline__ const float* pair_base(const float* x, int g) {
    const int n   = g >> 13;
    const int rem = g & 8191;
    const int h2  = rem >> 6;
    const int wq  = rem & 63;
    return x + ((size_t)n * C_IN * HIN + 2 * h2) * WIN + 4 * wq;
}

__global__ __launch_bounds__(256, 4) void fused_bn_relu_pool_conv(
    const float* __restrict__ x,
    const float* __restrict__ wmat,
    const float* __restrict__ scale,
    const float* __restrict__ bias,
    float* __restrict__ out)
{
    // Per-thread staging ring, depth 4: stage[k][r][tid] (r = 2x2-window row)
    __shared__ float4 stage[4][2][256];                 // 32 KB
    __shared__ float2 s_w2[C_IN * C_OUT];               // {0.25w, 0.25w}, 4 KB
    __shared__ float  s_sc[C_IN];
    __shared__ float  s_bi[C_IN];

    const int tid = threadIdx.x;
    for (int i = tid; i < C_IN * C_OUT; i += 256) {
        const float w = 0.25f * wmat[i];
        s_w2[i] = make_float2(w, w);
    }
    if (tid < C_IN) { s_sc[tid] = scale[tid]; s_bi[tid] = bias[tid]; }
    __syncthreads();

    // slot (k, r) lives at st0 + (k*2 + r) * 4096
    const unsigned int st0 = smem_u32(&stage[0][0][tid]);

    const int g0 = blockIdx.x * 256 + tid;
    const bool has2 = (g0 + GSTRIDE < TOTAL_PAIRS);

    const float* cur = pair_base(x, g0);
    const float* nxt = pair_base(x, has2 ? (g0 + GSTRIDE) : g0);

    // Prologue: channels 0..2 of the first pair (3 groups in flight)
#pragma unroll
    for (int k = 0; k < 3; k++) {
        cp16(st0 + (unsigned int)(k * 2 + 0) * 4096u, cur + (size_t)k * CSTRIDE);
        cp16(st0 + (unsigned int)(k * 2 + 1) * 4096u, cur + (size_t)k * CSTRIDE + WIN);
        cp_commit();
    }

    int g = g0;
    bool more = has2;

#pragma unroll 1
    for (int it = 0; it < 2; ++it) {
        unsigned long long acc[C_OUT];
#pragma unroll
        for (int d = 0; d < C_OUT; d++) acc[d] = 0ULL;

#pragma unroll
        for (int c = 0; c < C_IN; c++) {
            // Issue 3-ahead: channel c+3 of this pair, or channel c-29 of the
            // next pair (tail overlap), or an empty group (final iteration).
            const int a = c + 3;
            if (a < C_IN) {
                const unsigned int ks = (unsigned int)(a & 3);
                cp16(st0 + (ks * 2 + 0) * 4096u, cur + (size_t)a * CSTRIDE);
                cp16(st0 + (ks * 2 + 1) * 4096u, cur + (size_t)a * CSTRIDE + WIN);
            } else if (more) {
                const int an = a - C_IN;                // 0..2
                const unsigned int ks = (unsigned int)(an & 3);
                cp16(st0 + (ks * 2 + 0) * 4096u, nxt + (size_t)an * CSTRIDE);
                cp16(st0 + (ks * 2 + 1) * 4096u, nxt + (size_t)an * CSTRIDE + WIN);
            }
            cp_commit();          // empty group if nothing issued (completes at once)
            cp_wait<3>();         // channel c's group has landed

            const int k = c & 3;
            const float4 r0 = stage[k][0][tid];
            const float4 r1 = stage[k][1][tid];
            const float sc = s_sc[c];
            const float bi = s_bi[c];

            // BN + ReLU on all 8 taps
            const float v0 = fmaxf(fmaf(r0.x, sc, bi), 0.0f);
            const float v1 = fmaxf(fmaf(r0.y, sc, bi), 0.0f);
            const float v2 = fmaxf(fmaf(r0.z, sc, bi), 0.0f);
            const float v3 = fmaxf(fmaf(r0.w, sc, bi), 0.0f);
            const float u0 = fmaxf(fmaf(r1.x, sc, bi), 0.0f);
            const float u1 = fmaxf(fmaf(r1.y, sc, bi), 0.0f);
            const float u2 = fmaxf(fmaf(r1.z, sc, bi), 0.0f);
            const float u3 = fmaxf(fmaf(r1.w, sc, bi), 0.0f);

            // 2x2 pool sums (the *0.25 is folded into the weights)
            const float p0 = (v0 + v1) + (u0 + u1);
            const float p1 = (v2 + v3) + (u2 + u3);
            const unsigned long long p = pack_f32x2(p0, p1);

            const unsigned long long* w2 =
                reinterpret_cast<const unsigned long long*>(&s_w2[c * C_OUT]);
#pragma unroll
            for (int d = 0; d < C_OUT; d++) {
                fma_f32x2(acc[d], p, w2[d]);
            }
        }

        // Epilogue for pair g: out[n][d][h2][2*wq .. 2*wq+1]
        {
            const int n   = g >> 13;
            const int rem = g & 8191;
            const int h2  = rem >> 6;
            const int wq  = rem & 63;
            float2* o = reinterpret_cast<float2*>(
                out + (size_t)n * C_OUT * (POUT * POUT) + h2 * POUT + 2 * wq);
#pragma unroll
            for (int d = 0; d < C_OUT; d++) {
                o[(size_t)d * (POUT * POUT / 2)] =
                    *reinterpret_cast<const float2*>(&acc[d]);
            }
        }

        if (!more) break;
        g += GSTRIDE;
        cur = nxt;
        more = false;   // at most 2 pairs/thread with this grid
    }
}

extern "C" void kernel_launch(void* const* d_in, const int* in_sizes, int n_in,
                              void* d_out, int out_size)
{
    const float* x     = (const float*)d_in[0];
    const float* wmat  = (const float*)d_in[1];
    const float* scale = (const float*)d_in[2];
    const float* bias  = (const float*)d_in[3];
    float* out         = (float*)d_out;

    // Persistent single wave: 592 blocks = 4/SM * 148 SMs; 432 blocks carry
    // 2 pixel-pairs/thread, 160 carry 1 -> 98.8% fill, pipeline never drains.
    fused_bn_relu_pool_conv<<<NBLOCKS, 256>>>(x, wmat, scale, bias, out);
}